// round 1
// baseline (speedup 1.0000x reference)
#include <cuda_runtime.h>
#include <cstdint>

// Problem constants
#define BB 4096
#define LL 50
#define DD 200
#define NBLK 3
#define NTH 224              // 7 warps; threads 0..199 own output column d

#define NEGF  (-4294967295.0f)
#define EPSF  (1e-8f)
#define SCALE (0.07071067811865475f)   // 1/sqrt(200)

// SMEM layout (floats)
#define OFF_XS   0
#define OFF_QS   10000
#define OFF_KS   20000
#define OFF_VS   30000
#define OFF_SC   40000      // 50 x 52 (padded row stride)
#define OFF_RED  42600      // 50 x 4 reduction partials
#define OFF_RM   42800      // 50 row masks (1 = valid)
#define OFF_MU   42850      // 50
#define OFF_RSD  42900      // 50
#define SMEM_FLOATS 42950
#define SMEM_BYTES (SMEM_FLOATS * 4)

// out[l][d] = act( sum_k A[l][k] * W[k*200+d] + bias[d] ), for d = tid, all 50 l.
// One weight LDG is reused across 50 row-accumulators; A reads are float4
// broadcasts (all lanes same address -> conflict-free).
template <bool RELU>
__device__ __forceinline__ void mm200(const float* __restrict__ A,
                                      const float* __restrict__ W,
                                      const float* __restrict__ bias,
                                      float* __restrict__ O, int tid) {
    if (tid >= DD) return;
    const int d = tid;
    float acc[LL];
    const float bv = bias[d];
#pragma unroll
    for (int l = 0; l < LL; ++l) acc[l] = bv;

    const float* wp = W + d;
#pragma unroll 1
    for (int k = 0; k < DD; k += 4) {
        const float w0 = wp[0];
        const float w1 = wp[DD];
        const float w2 = wp[2 * DD];
        const float w3 = wp[3 * DD];
        wp += 4 * DD;
#pragma unroll
        for (int l = 0; l < LL; ++l) {
            const float4 x = *(const float4*)(A + l * DD + k);
            float a = acc[l];
            a = fmaf(x.x, w0, a);
            a = fmaf(x.y, w1, a);
            a = fmaf(x.z, w2, a);
            a = fmaf(x.w, w3, a);
            acc[l] = a;
        }
    }
#pragma unroll
    for (int l = 0; l < LL; ++l)
        O[l * DD + d] = RELU ? fmaxf(acc[l], 0.0f) : acc[l];
}

__global__ __launch_bounds__(NTH, 1)
void transformer_rows_kernel(const int* __restrict__ tokens,
                             const float* __restrict__ emb,
                             const float* __restrict__ Wq, const float* __restrict__ bq,
                             const float* __restrict__ Wk, const float* __restrict__ bk,
                             const float* __restrict__ Wv, const float* __restrict__ bv,
                             const float* __restrict__ W1, const float* __restrict__ b1,
                             const float* __restrict__ W2, const float* __restrict__ b2,
                             const float* __restrict__ lng, const float* __restrict__ lnb,
                             float* __restrict__ out) {
    extern __shared__ float sm[];
    float* XS  = sm + OFF_XS;
    float* QS  = sm + OFF_QS;
    float* KS  = sm + OFF_KS;
    float* VS  = sm + OFF_VS;
    float* SC  = sm + OFF_SC;
    float* RED = sm + OFF_RED;
    float* RM  = sm + OFF_RM;
    float* MU  = sm + OFF_MU;
    float* RSD = sm + OFF_RSD;

    const int b   = blockIdx.x;
    const int tid = threadIdx.x;

    // ---- embedding gather: x = emb[tokens[b]] ----
    const int* tok = tokens + b * LL;
    for (int i = tid; i < LL * DD; i += NTH) {
        const int l = i / DD;
        const int d = i - l * DD;
        XS[i] = emb[tok[l] * DD + d];
    }
    __syncthreads();

    for (int blk = 0; blk < NBLK; ++blk) {
        const float* wq  = Wq  + blk * DD * DD;  const float* bqv = bq  + blk * DD;
        const float* wk  = Wk  + blk * DD * DD;  const float* bkv = bk  + blk * DD;
        const float* wv  = Wv  + blk * DD * DD;  const float* bvv = bv  + blk * DD;
        const float* w1  = W1  + blk * DD * DD;  const float* b1v = b1  + blk * DD;
        const float* w2  = W2  + blk * DD * DD;  const float* b2v = b2  + blk * DD;
        const float* gv  = lng + blk * DD;       const float* bnv = lnb + blk * DD;

        // ---- row mask: valid iff sum_d x[l][d] != 0 ----
        if (tid < 200) {
            const int l = tid >> 2, q = tid & 3;
            const float* row = XS + l * DD + q * 50;
            float s = 0.0f;
#pragma unroll
            for (int k = 0; k < 50; ++k) s += row[k];
            RED[tid] = s;
        }
        __syncthreads();
        if (tid < LL) {
            const float s = RED[tid * 4] + RED[tid * 4 + 1] + RED[tid * 4 + 2] + RED[tid * 4 + 3];
            RM[tid] = (s != 0.0f) ? 1.0f : 0.0f;
        }

        // ---- Q, K, V = relu(x @ W + b) ----
        mm200<true>(XS, wq, bqv, QS, tid);
        mm200<true>(XS, wk, bkv, KS, tid);
        mm200<true>(XS, wv, bvv, VS, tid);
        __syncthreads();

        // ---- scores[l][m] = (Q[l] . K[m]) * SCALE, masked keys -> NEG ----
        if (tid < 200) {
            const int m = tid % 50;
            const int g = tid / 50;
            const int lo = g * 13;
            float acc[13];
#pragma unroll
            for (int j = 0; j < 13; ++j) acc[j] = 0.0f;
#pragma unroll 1
            for (int dd4 = 0; dd4 < DD; dd4 += 4) {
                const float4 kv = *(const float4*)(KS + m * DD + dd4);
#pragma unroll
                for (int j = 0; j < 13; ++j) {
                    const int l = lo + j;
                    if (l < LL) {
                        const float4 qv = *(const float4*)(QS + l * DD + dd4);
                        float a = acc[j];
                        a = fmaf(qv.x, kv.x, a);
                        a = fmaf(qv.y, kv.y, a);
                        a = fmaf(qv.z, kv.z, a);
                        a = fmaf(qv.w, kv.w, a);
                        acc[j] = a;
                    }
                }
            }
            const float keep = RM[m];
#pragma unroll
            for (int j = 0; j < 13; ++j) {
                const int l = lo + j;
                if (l < LL) SC[l * 52 + m] = (keep != 0.0f) ? acc[j] * SCALE : NEGF;
            }
        }
        __syncthreads();

        // ---- softmax per row (includes NEG entries), then * qmask ----
        if (tid < LL) {
            float* r = SC + tid * 52;
            float mx = r[0];
#pragma unroll
            for (int m = 1; m < 50; ++m) mx = fmaxf(mx, r[m]);
            float s = 0.0f;
#pragma unroll
            for (int m = 0; m < 50; ++m) {
                const float e = expf(r[m] - mx);
                r[m] = e;
                s += e;
            }
            const float inv = RM[tid] / s;
#pragma unroll
            for (int m = 0; m < 50; ++m) r[m] *= inv;
        }
        __syncthreads();

        // ---- x = attn @ V + x  (in place) ----
        if (tid < 200) {
            const int d = tid;
            float acc[LL];
#pragma unroll
            for (int l = 0; l < LL; ++l) acc[l] = 0.0f;
#pragma unroll 1
            for (int m = 0; m < 50; m += 2) {
                const float v0 = VS[m * DD + d];
                const float v1 = VS[(m + 1) * DD + d];
#pragma unroll
                for (int l = 0; l < LL; ++l) {
                    const float2 a = *(const float2*)(SC + l * 52 + m);
                    acc[l] = fmaf(a.x, v0, fmaf(a.y, v1, acc[l]));
                }
            }
#pragma unroll
            for (int l = 0; l < LL; ++l) XS[l * DD + d] += acc[l];
        }
        __syncthreads();

        // ---- FFN: h1 = relu(x@W1+b1); h2 = h1@W2+b2 ----
        mm200<true>(XS, w1, b1v, QS, tid);
        __syncthreads();
        mm200<false>(QS, w2, b2v, KS, tid);
        __syncthreads();

        // ---- layernorm(h2)*g + b + x -> x ----
        if (tid < 200) {
            const int l = tid >> 2, q = tid & 3;
            const float* row = KS + l * DD + q * 50;
            float s = 0.0f;
#pragma unroll
            for (int k = 0; k < 50; ++k) s += row[k];
            RED[tid] = s;
        }
        __syncthreads();
        if (tid < LL)
            MU[tid] = (RED[tid * 4] + RED[tid * 4 + 1] + RED[tid * 4 + 2] + RED[tid * 4 + 3]) * (1.0f / DD);
        __syncthreads();
        if (tid < 200) {
            const int l = tid >> 2, q = tid & 3;
            const float mu = MU[l];
            const float* row = KS + l * DD + q * 50;
            float s = 0.0f;
#pragma unroll
            for (int k = 0; k < 50; ++k) {
                const float dv = row[k] - mu;
                s = fmaf(dv, dv, s);
            }
            RED[tid] = s;
        }
        __syncthreads();
        if (tid < LL) {
            const float var = (RED[tid * 4] + RED[tid * 4 + 1] + RED[tid * 4 + 2] + RED[tid * 4 + 3]) * (1.0f / DD);
            RSD[tid] = rsqrtf(var + EPSF);
        }
        __syncthreads();
        if (tid < 200) {
            const int d = tid;
            const float g = gv[d];
            const float bb = bnv[d];
#pragma unroll 1
            for (int l = 0; l < LL; ++l) {
                XS[l * DD + d] += (KS[l * DD + d] - MU[l]) * RSD[l] * g + bb;
            }
        }
        __syncthreads();
    }

    // ---- write result ----
    float* ob = out + (size_t)b * LL * DD;
    for (int i = tid; i < LL * DD; i += NTH) ob[i] = XS[i];
}

extern "C" void kernel_launch(void* const* d_in, const int* in_sizes, int n_in,
                              void* d_out, int out_size) {
    (void)in_sizes; (void)n_in; (void)out_size;
    const int*   tokens = (const int*)  d_in[0];
    const float* emb    = (const float*)d_in[1];
    const float* Wq     = (const float*)d_in[2];
    const float* bq     = (const float*)d_in[3];
    const float* Wk     = (const float*)d_in[4];
    const float* bk     = (const float*)d_in[5];
    const float* Wv     = (const float*)d_in[6];
    const float* bv     = (const float*)d_in[7];
    const float* W1     = (const float*)d_in[8];
    const float* b1     = (const float*)d_in[9];
    const float* W2     = (const float*)d_in[10];
    const float* b2     = (const float*)d_in[11];
    const float* lng    = (const float*)d_in[12];
    const float* lnb    = (const float*)d_in[13];
    float* out = (float*)d_out;

    cudaFuncSetAttribute(transformer_rows_kernel,
                         cudaFuncAttributeMaxDynamicSharedMemorySize, SMEM_BYTES);
    transformer_rows_kernel<<<BB, NTH, SMEM_BYTES>>>(
        tokens, emb, Wq, bq, Wk, bk, Wv, bv, W1, b1, W2, b2, lng, lnb, out);
}

// round 4
// speedup vs baseline: 1.1098x; 1.1098x over previous
#include <cuda_runtime.h>
#include <cstdint>

// Problem constants
#define BB 4096
#define LL 50
#define LP 25              // row pairs (l, l+25)
#define DD 200
#define NBLK 3
#define NTH 224            // 7 warps; threads 0..199 active in compute stages

#define NEGF  (-4294967295.0f)
#define EPSF  (1e-8f)
#define SCALEF (0.07071067811865475f)   // 1/sqrt(200)

typedef unsigned long long u64;

// ---- packed f32x2 helpers ----
__device__ __forceinline__ u64 pk2(float lo, float hi) {
    u64 r; asm("mov.b64 %0, {%1, %2};" : "=l"(r) : "f"(lo), "f"(hi)); return r;
}
__device__ __forceinline__ void upk2(u64 v, float& lo, float& hi) {
    asm("mov.b64 {%0, %1}, %2;" : "=f"(lo), "=f"(hi) : "l"(v));
}
__device__ __forceinline__ u64 fma2(u64 a, u64 b, u64 c) {
    u64 d; asm("fma.rn.f32x2 %0, %1, %2, %3;" : "=l"(d) : "l"(a), "l"(b), "l"(c)); return d;
}
__device__ __forceinline__ u64 add2(u64 a, u64 b) {
    u64 d; asm("add.rn.f32x2 %0, %1, %2;" : "=l"(d) : "l"(a), "l"(b)); return d;
}

// SMEM layout (float offsets)
// Pair-interleaved matrices: elem (l = lp + 25*h, d) lives at 2*(lp*200 + d) + h.
// Row-major-201 matrices: elem (l, d) at l*201 + d.
#define OFF_XI   0          // x, pair layout (10000)
#define OFF_QB   10000      // Q then h1, pair layout (10000)
#define OFF_KB   20000      // K then h2, row-major-201 (10056)
#define OFF_VB   30056      // V, row-major-201 (10056)
#define OFF_SC   40112      // scores, pair layout stride 52 (5200)
#define OFF_RED  45312      // u64[200] partials (=400 floats)
#define OFF_RM   45712      // 50 row masks
#define OFF_MU   45762      // 50
#define OFF_RSD  45812      // 50
#define SMEM_FLOATS 45862
#define SMEM_BYTES (SMEM_FLOATS * 4)

// Pair GEMM: O[l][d] = act( sum_k A[l][k] * W[k*200+d] + bias[d] )
// A in pair layout. Thread (c = tid%50, g = tid/50) owns cols {c,c+50,c+100,c+150}
// and row-pairs lp in {g, g+4, ...}. Accumulators are f32x2 (rows l, l+25).
template <bool RELU, bool PAIRS_OUT>
__device__ __forceinline__ void mm200p(const float* __restrict__ AI,
                                       const float* __restrict__ W,
                                       const float* __restrict__ bias,
                                       float* __restrict__ O, int tid) {
    if (tid >= 200) return;
    const int c = tid % 50;
    const int g = tid / 50;
    const int R = (g == 0) ? 7 : 6;

    u64 acc[7][4];
    {
        const u64 pb0 = pk2(bias[c], bias[c]);
        const u64 pb1 = pk2(bias[c + 50], bias[c + 50]);
        const u64 pb2 = pk2(bias[c + 100], bias[c + 100]);
        const u64 pb3 = pk2(bias[c + 150], bias[c + 150]);
#pragma unroll
        for (int r = 0; r < 7; ++r) {
            acc[r][0] = pb0; acc[r][1] = pb1; acc[r][2] = pb2; acc[r][3] = pb3;
        }
    }

#pragma unroll 2
    for (int k2 = 0; k2 < 100; ++k2) {
        const float* wr0 = W + (2 * k2) * DD + c;
        const float* wr1 = wr0 + DD;
        const u64 p00 = pk2(wr0[0], wr0[0]);
        const u64 p01 = pk2(wr0[50], wr0[50]);
        const u64 p02 = pk2(wr0[100], wr0[100]);
        const u64 p03 = pk2(wr0[150], wr0[150]);
        const u64 p10 = pk2(wr1[0], wr1[0]);
        const u64 p11 = pk2(wr1[50], wr1[50]);
        const u64 p12 = pk2(wr1[100], wr1[100]);
        const u64 p13 = pk2(wr1[150], wr1[150]);
#pragma unroll
        for (int r = 0; r < 7; ++r) {
            if (r < R) {
                const int lp = g + 4 * r;
                const ulonglong2 x = *(const ulonglong2*)(AI + 2 * (lp * DD + 2 * k2));
                acc[r][0] = fma2(x.x, p00, acc[r][0]);
                acc[r][1] = fma2(x.x, p01, acc[r][1]);
                acc[r][2] = fma2(x.x, p02, acc[r][2]);
                acc[r][3] = fma2(x.x, p03, acc[r][3]);
                acc[r][0] = fma2(x.y, p10, acc[r][0]);
                acc[r][1] = fma2(x.y, p11, acc[r][1]);
                acc[r][2] = fma2(x.y, p12, acc[r][2]);
                acc[r][3] = fma2(x.y, p13, acc[r][3]);
            }
        }
    }

#pragma unroll
    for (int r = 0; r < 7; ++r) {
        if (r < R) {
            const int lp = g + 4 * r;
#pragma unroll
            for (int j = 0; j < 4; ++j) {
                float lo, hi;
                upk2(acc[r][j], lo, hi);
                if (RELU) { lo = fmaxf(lo, 0.0f); hi = fmaxf(hi, 0.0f); }
                const int col = c + j * 50;
                if (PAIRS_OUT) {
                    *(u64*)(O + 2 * (lp * DD + col)) = pk2(lo, hi);
                } else {
                    O[lp * 201 + col] = lo;
                    O[(lp + 25) * 201 + col] = hi;
                }
            }
        }
    }
}

__global__ __launch_bounds__(NTH, 1)
void transformer_rows_kernel(const int* __restrict__ tokens,
                             const float* __restrict__ emb,
                             const float* __restrict__ Wq, const float* __restrict__ bq,
                             const float* __restrict__ Wk, const float* __restrict__ bk,
                             const float* __restrict__ Wv, const float* __restrict__ bv,
                             const float* __restrict__ W1, const float* __restrict__ b1,
                             const float* __restrict__ W2, const float* __restrict__ b2,
                             const float* __restrict__ lng, const float* __restrict__ lnb,
                             float* __restrict__ out) {
    extern __shared__ float sm[];
    float* XI  = sm + OFF_XI;
    float* QB  = sm + OFF_QB;
    float* KB  = sm + OFF_KB;
    float* VB  = sm + OFF_VB;
    float* SC  = sm + OFF_SC;
    u64*   REDU = (u64*)(sm + OFF_RED);
    float* REDF = sm + OFF_RED;
    float* RM  = sm + OFF_RM;
    float* MU  = sm + OFF_MU;
    float* RSD = sm + OFF_RSD;

    const int b   = blockIdx.x;
    const int tid = threadIdx.x;

    // ---- embedding gather into pair layout ----
    const int* tok = tokens + b * LL;
    for (int i = tid; i < LP * DD; i += NTH) {
        const int lp = i / DD;
        const int d  = i - lp * DD;
        const float v0 = emb[tok[lp] * DD + d];
        const float v1 = emb[tok[lp + 25] * DD + d];
        *(u64*)(XI + 2 * i) = pk2(v0, v1);
    }
    __syncthreads();

    for (int blk = 0; blk < NBLK; ++blk) {
        const float* wq  = Wq  + blk * DD * DD;  const float* bqv = bq  + blk * DD;
        const float* wk  = Wk  + blk * DD * DD;  const float* bkv = bk  + blk * DD;
        const float* wv  = Wv  + blk * DD * DD;  const float* bvv = bv  + blk * DD;
        const float* w1  = W1  + blk * DD * DD;  const float* b1v = b1  + blk * DD;
        const float* w2  = W2  + blk * DD * DD;  const float* b2v = b2  + blk * DD;
        const float* gv  = lng + blk * DD;       const float* bnv = lnb + blk * DD;

        // ---- row-sum mask, part A (per-pair partial sums over 25-col chunks) ----
        if (tid < 200) {
            const int lp = tid >> 3, oct = tid & 7;
            const float* base = XI + 2 * (lp * DD + oct * 25);
            u64 s = 0;  // bit pattern of (0.0f, 0.0f)
#pragma unroll
            for (int k = 0; k < 25; ++k) s = add2(s, *(const u64*)(base + 2 * k));
            REDU[tid] = s;
        }
        __syncthreads();
        // ---- part B + QKV projections ----
        if (tid < 25) {
            u64 s = REDU[tid * 8];
#pragma unroll
            for (int j = 1; j < 8; ++j) s = add2(s, REDU[tid * 8 + j]);
            float lo, hi; upk2(s, lo, hi);
            RM[tid]      = (lo != 0.0f) ? 1.0f : 0.0f;
            RM[tid + 25] = (hi != 0.0f) ? 1.0f : 0.0f;
        }
        mm200p<true, true >(XI, wq, bqv, QB, tid);   // Q pair layout
        mm200p<true, false>(XI, wk, bkv, KB, tid);   // K row-major-201
        mm200p<true, false>(XI, wv, bvv, VB, tid);   // V row-major-201
        __syncthreads();

        // ---- scores: query pair (lp, lp+25) packed, key m per thread ----
        if (tid < 200) {
            const int m = tid % 50;
            const int g = tid / 50;
            const int T = (g == 0) ? 7 : 6;
            const float* Krow = KB + m * 201;
            u64 acc[7];
#pragma unroll
            for (int r = 0; r < 7; ++r) acc[r] = 0;
#pragma unroll 2
            for (int k2 = 0; k2 < 100; ++k2) {
                const int k = 2 * k2;
                const u64 pa = pk2(Krow[k], Krow[k]);
                const u64 pb = pk2(Krow[k + 1], Krow[k + 1]);
#pragma unroll
                for (int r = 0; r < 7; ++r) {
                    if (r < T) {
                        const int lp = g + 4 * r;
                        const ulonglong2 q = *(const ulonglong2*)(QB + 2 * (lp * DD + k));
                        acc[r] = fma2(q.x, pa, acc[r]);
                        acc[r] = fma2(q.y, pb, acc[r]);
                    }
                }
            }
            const bool keep = (RM[m] != 0.0f);
#pragma unroll
            for (int r = 0; r < 7; ++r) {
                if (r < T) {
                    const int lp = g + 4 * r;
                    float lo, hi; upk2(acc[r], lo, hi);
                    const float s0 = keep ? lo * SCALEF : NEGF;
                    const float s1 = keep ? hi * SCALEF : NEGF;
                    *(u64*)(SC + 2 * (lp * 52 + m)) = pk2(s0, s1);
                }
            }
        }
        __syncthreads();

        // ---- softmax per query row, * qmask ----
        if (tid < LL) {
            const int lp = tid % 25, h = tid / 25;
            float* base = SC + 2 * (lp * 52) + h;
            float mx = base[0];
#pragma unroll
            for (int m = 1; m < 50; ++m) mx = fmaxf(mx, base[2 * m]);
            float s = 0.0f;
#pragma unroll
            for (int m = 0; m < 50; ++m) {
                const float e = expf(base[2 * m] - mx);
                base[2 * m] = e;
                s += e;
            }
            const float inv = RM[tid] / s;
#pragma unroll
            for (int m = 0; m < 50; ++m) base[2 * m] *= inv;
        }
        __syncthreads();

        // ---- x += attn @ V ----
        if (tid < 200) {
            const int d = tid;
            u64 acc[25];
#pragma unroll
            for (int lp = 0; lp < 25; ++lp) acc[lp] = 0;
#pragma unroll 2
            for (int m = 0; m < 50; ++m) {
                const float v = VB[m * 201 + d];
                const u64 pv = pk2(v, v);
#pragma unroll
                for (int lp = 0; lp < 25; ++lp) {
                    const u64 a = *(const u64*)(SC + 2 * (lp * 52 + m));
                    acc[lp] = fma2(a, pv, acc[lp]);
                }
            }
#pragma unroll
            for (int lp = 0; lp < 25; ++lp) {
                u64* p = (u64*)(XI + 2 * (lp * DD + d));
                *p = add2(*p, acc[lp]);
            }
        }
        __syncthreads();

        // ---- FFN: h1 = relu(x@W1+b1) (pairs), h2 = h1@W2+b2 (row-major-201) ----
        mm200p<true, true >(XI, w1, b1v, QB, tid);
        __syncthreads();
        mm200p<false, false>(QB, w2, b2v, KB, tid);
        __syncthreads();

        // ---- layernorm(h2)*g + b + x -> x ----
        if (tid < 200) {
            const int l = tid >> 2, q = tid & 3;
            const float* row = KB + l * 201 + q * 50;
            float s = 0.0f;
#pragma unroll
            for (int k = 0; k < 50; ++k) s += row[k];
            REDF[tid] = s;
        }
        __syncthreads();
        if (tid < LL)
            MU[tid] = (REDF[tid * 4] + REDF[tid * 4 + 1] + REDF[tid * 4 + 2] + REDF[tid * 4 + 3]) * (1.0f / DD);
        __syncthreads();
        if (tid < 200) {
            const int l = tid >> 2, q = tid & 3;
            const float mu = MU[l];
            const float* row = KB + l * 201 + q * 50;
            float s = 0.0f;
#pragma unroll
            for (int k = 0; k < 50; ++k) {
                const float dv = row[k] - mu;
                s = fmaf(dv, dv, s);
            }
            REDF[tid] = s;
        }
        __syncthreads();
        if (tid < LL) {
            const float var = (REDF[tid * 4] + REDF[tid * 4 + 1] + REDF[tid * 4 + 2] + REDF[tid * 4 + 3]) * (1.0f / DD);
            RSD[tid] = rsqrtf(var + EPSF);
        }
        __syncthreads();
        if (tid < 200) {
            const int d = tid;
            const float gd = gv[d];
            const float bd = bnv[d];
#pragma unroll 1
            for (int lp = 0; lp < 25; ++lp) {
                const float lo = (KB[lp * 201 + d]        - MU[lp])      * RSD[lp]      * gd + bd;
                const float hi = (KB[(lp + 25) * 201 + d] - MU[lp + 25]) * RSD[lp + 25] * gd + bd;
                u64* p = (u64*)(XI + 2 * (lp * DD + d));
                *p = add2(*p, pk2(lo, hi));
            }
        }
        __syncthreads();
    }

    // ---- write result (de-interleave) ----
    float* ob = out + (size_t)b * LL * DD;
    for (int i = tid; i < LP * DD; i += NTH) {
        const int lp = i / DD;
        const int d  = i - lp * DD;
        float lo, hi;
        upk2(*(const u64*)(XI + 2 * i), lo, hi);
        ob[lp * DD + d] = lo;
        ob[(lp + 25) * DD + d] = hi;
    }
}

extern "C" void kernel_launch(void* const* d_in, const int* in_sizes, int n_in,
                              void* d_out, int out_size) {
    (void)in_sizes; (void)n_in; (void)out_size;
    const int*   tokens = (const int*)  d_in[0];
    const float* emb    = (const float*)d_in[1];
    const float* Wq     = (const float*)d_in[2];
    const float* bq     = (const float*)d_in[3];
    const float* Wk     = (const float*)d_in[4];
    const float* bk     = (const float*)d_in[5];
    const float* Wv     = (const float*)d_in[6];
    const float* bv     = (const float*)d_in[7];
    const float* W1     = (const float*)d_in[8];
    const float* b1     = (const float*)d_in[9];
    const float* W2     = (const float*)d_in[10];
    const float* b2     = (const float*)d_in[11];
    const float* lng    = (const float*)d_in[12];
    const float* lnb    = (const float*)d_in[13];
    float* out = (float*)d_out;

    cudaFuncSetAttribute(transformer_rows_kernel,
                         cudaFuncAttributeMaxDynamicSharedMemorySize, SMEM_BYTES);
    transformer_rows_kernel<<<BB, NTH, SMEM_BYTES>>>(
        tokens, emb, Wq, bq, Wk, bk, Wv, bv, W1, b1, W2, b2, lng, lnb, out);
}

// round 5
// speedup vs baseline: 1.1611x; 1.0462x over previous
#include <cuda_runtime.h>
#include <cstdint>

// Problem constants
#define BB 4096
#define LL 50
#define LP 25              // row pairs (l, l+25)
#define DD 200
#define NBLK 3
#define NTH 448            // 14 warps; threads 0..399 active in big compute stages

#define NEGF  (-4294967295.0f)
#define EPSF  (1e-8f)
#define SCALEF (0.07071067811865475f)   // 1/sqrt(200)

typedef unsigned long long u64;

// ---- packed f32x2 helpers ----
__device__ __forceinline__ u64 pk2(float lo, float hi) {
    u64 r; asm("mov.b64 %0, {%1, %2};" : "=l"(r) : "f"(lo), "f"(hi)); return r;
}
__device__ __forceinline__ void upk2(u64 v, float& lo, float& hi) {
    asm("mov.b64 {%0, %1}, %2;" : "=f"(lo), "=f"(hi) : "l"(v));
}
__device__ __forceinline__ u64 fma2(u64 a, u64 b, u64 c) {
    u64 d; asm("fma.rn.f32x2 %0, %1, %2, %3;" : "=l"(d) : "l"(a), "l"(b), "l"(c)); return d;
}
__device__ __forceinline__ u64 add2(u64 a, u64 b) {
    u64 d; asm("add.rn.f32x2 %0, %1, %2;" : "=l"(d) : "l"(a), "l"(b)); return d;
}

// SMEM layout (float offsets)
// Pair-interleaved matrices: elem (l = lp + 25*h, d) lives at 2*(lp*200 + d) + h.
// Row-major-201 matrices: elem (l, d) at l*201 + d.
#define OFF_XI   0          // x, pair layout (10000)
#define OFF_QB   10000      // Q then h1, pair layout (10000)
#define OFF_KB   20000      // K then h2, row-major-201 (10056)
#define OFF_VB   30056      // V, row-major-201 (10056)
#define OFF_SC   40112      // scores, pair layout stride 52 (2600)
#define OFF_RED  42712      // u64[200] partials (=400 floats, also used as float[400])
#define OFF_RM   43112      // 50 row masks
#define OFF_MU   43162      // 50
#define OFF_RSD  43212      // 50
#define SMEM_FLOATS 43264
#define SMEM_BYTES (SMEM_FLOATS * 4)

// Pair GEMM: O[l][d] = act( sum_k A[l][k] * W[k*200+d] + bias[d] )
// A in pair layout. Thread (c = tid%50, g = tid/50, g<8) owns cols
// {c,c+50,c+100,c+150} and row-pairs lp in {g, g+8, g+16, (g==0: 24)}.
template <bool RELU, bool PAIRS_OUT>
__device__ __forceinline__ void mm200p(const float* __restrict__ AI,
                                       const float* __restrict__ W,
                                       const float* __restrict__ bias,
                                       float* __restrict__ O, int tid) {
    if (tid >= 400) return;
    const int c = tid % 50;
    const int g = tid / 50;            // 0..7
    const int R = (g == 0) ? 4 : 3;    // lp = g + 8*r < 25

    u64 acc[4][4];
    {
        const u64 pb0 = pk2(bias[c], bias[c]);
        const u64 pb1 = pk2(bias[c + 50], bias[c + 50]);
        const u64 pb2 = pk2(bias[c + 100], bias[c + 100]);
        const u64 pb3 = pk2(bias[c + 150], bias[c + 150]);
#pragma unroll
        for (int r = 0; r < 4; ++r) {
            acc[r][0] = pb0; acc[r][1] = pb1; acc[r][2] = pb2; acc[r][3] = pb3;
        }
    }

#pragma unroll 2
    for (int k2 = 0; k2 < 100; ++k2) {
        const float* wr0 = W + (2 * k2) * DD + c;
        const float* wr1 = wr0 + DD;
        const u64 p00 = pk2(wr0[0], wr0[0]);
        const u64 p01 = pk2(wr0[50], wr0[50]);
        const u64 p02 = pk2(wr0[100], wr0[100]);
        const u64 p03 = pk2(wr0[150], wr0[150]);
        const u64 p10 = pk2(wr1[0], wr1[0]);
        const u64 p11 = pk2(wr1[50], wr1[50]);
        const u64 p12 = pk2(wr1[100], wr1[100]);
        const u64 p13 = pk2(wr1[150], wr1[150]);
#pragma unroll
        for (int r = 0; r < 4; ++r) {
            if (r < R) {
                const int lp = g + 8 * r;
                const ulonglong2 x = *(const ulonglong2*)(AI + 2 * (lp * DD + 2 * k2));
                acc[r][0] = fma2(x.x, p00, acc[r][0]);
                acc[r][1] = fma2(x.x, p01, acc[r][1]);
                acc[r][2] = fma2(x.x, p02, acc[r][2]);
                acc[r][3] = fma2(x.x, p03, acc[r][3]);
                acc[r][0] = fma2(x.y, p10, acc[r][0]);
                acc[r][1] = fma2(x.y, p11, acc[r][1]);
                acc[r][2] = fma2(x.y, p12, acc[r][2]);
                acc[r][3] = fma2(x.y, p13, acc[r][3]);
            }
        }
    }

#pragma unroll
    for (int r = 0; r < 4; ++r) {
        if (r < R) {
            const int lp = g + 8 * r;
#pragma unroll
            for (int j = 0; j < 4; ++j) {
                float lo, hi;
                upk2(acc[r][j], lo, hi);
                if (RELU) { lo = fmaxf(lo, 0.0f); hi = fmaxf(hi, 0.0f); }
                const int col = c + j * 50;
                if (PAIRS_OUT) {
                    *(u64*)(O + 2 * (lp * DD + col)) = pk2(lo, hi);
                } else {
                    O[lp * 201 + col] = lo;
                    O[(lp + 25) * 201 + col] = hi;
                }
            }
        }
    }
}

__global__ __launch_bounds__(NTH, 1)
void transformer_rows_kernel(const int* __restrict__ tokens,
                             const float* __restrict__ emb,
                             const float* __restrict__ Wq, const float* __restrict__ bq,
                             const float* __restrict__ Wk, const float* __restrict__ bk,
                             const float* __restrict__ Wv, const float* __restrict__ bv,
                             const float* __restrict__ W1, const float* __restrict__ b1,
                             const float* __restrict__ W2, const float* __restrict__ b2,
                             const float* __restrict__ lng, const float* __restrict__ lnb,
                             float* __restrict__ out) {
    extern __shared__ float sm[];
    float* XI  = sm + OFF_XI;
    float* QB  = sm + OFF_QB;
    float* KB  = sm + OFF_KB;
    float* VB  = sm + OFF_VB;
    float* SC  = sm + OFF_SC;
    u64*   REDU = (u64*)(sm + OFF_RED);
    float* REDF = sm + OFF_RED;
    float* RM  = sm + OFF_RM;
    float* MU  = sm + OFF_MU;
    float* RSD = sm + OFF_RSD;

    const int b   = blockIdx.x;
    const int tid = threadIdx.x;

    // ---- embedding gather into pair layout ----
    const int* tok = tokens + b * LL;
    for (int i = tid; i < LP * DD; i += NTH) {
        const int lp = i / DD;
        const int d  = i - lp * DD;
        const float v0 = emb[tok[lp] * DD + d];
        const float v1 = emb[tok[lp + 25] * DD + d];
        *(u64*)(XI + 2 * i) = pk2(v0, v1);
    }
    __syncthreads();

    for (int blk = 0; blk < NBLK; ++blk) {
        const float* wq  = Wq  + blk * DD * DD;  const float* bqv = bq  + blk * DD;
        const float* wk  = Wk  + blk * DD * DD;  const float* bkv = bk  + blk * DD;
        const float* wv  = Wv  + blk * DD * DD;  const float* bvv = bv  + blk * DD;
        const float* w1  = W1  + blk * DD * DD;  const float* b1v = b1  + blk * DD;
        const float* w2  = W2  + blk * DD * DD;  const float* b2v = b2  + blk * DD;
        const float* gv  = lng + blk * DD;       const float* bnv = lnb + blk * DD;

        // ---- row-sum mask, part A (per-pair partial sums over 25-col chunks) ----
        if (tid < 200) {
            const int lp = tid >> 3, oct = tid & 7;
            const float* base = XI + 2 * (lp * DD + oct * 25);
            u64 s = 0;  // bit pattern of (0.0f, 0.0f)
#pragma unroll
            for (int k = 0; k < 25; ++k) s = add2(s, *(const u64*)(base + 2 * k));
            REDU[tid] = s;
        }
        __syncthreads();
        // ---- part B + QKV projections ----
        if (tid < 25) {
            u64 s = REDU[tid * 8];
#pragma unroll
            for (int j = 1; j < 8; ++j) s = add2(s, REDU[tid * 8 + j]);
            float lo, hi; upk2(s, lo, hi);
            RM[tid]      = (lo != 0.0f) ? 1.0f : 0.0f;
            RM[tid + 25] = (hi != 0.0f) ? 1.0f : 0.0f;
        }
        mm200p<true, true >(XI, wq, bqv, QB, tid);   // Q pair layout
        mm200p<true, false>(XI, wk, bkv, KB, tid);   // K row-major-201
        mm200p<true, false>(XI, wv, bvv, VB, tid);   // V row-major-201
        __syncthreads();

        // ---- scores: query pair (lp, lp+25) packed, key m per thread ----
        if (tid < 400) {
            const int m = tid % 50;
            const int g = tid / 50;            // 0..7
            const int T = (g == 0) ? 4 : 3;
            const float* Krow = KB + m * 201;
            u64 acc[4];
#pragma unroll
            for (int r = 0; r < 4; ++r) acc[r] = 0;
#pragma unroll 2
            for (int k2 = 0; k2 < 100; ++k2) {
                const int k = 2 * k2;
                const u64 pa = pk2(Krow[k], Krow[k]);
                const u64 pb = pk2(Krow[k + 1], Krow[k + 1]);
#pragma unroll
                for (int r = 0; r < 4; ++r) {
                    if (r < T) {
                        const int lp = g + 8 * r;
                        const ulonglong2 q = *(const ulonglong2*)(QB + 2 * (lp * DD + k));
                        acc[r] = fma2(q.x, pa, acc[r]);
                        acc[r] = fma2(q.y, pb, acc[r]);
                    }
                }
            }
            const bool keep = (RM[m] != 0.0f);
#pragma unroll
            for (int r = 0; r < 4; ++r) {
                if (r < T) {
                    const int lp = g + 8 * r;
                    float lo, hi; upk2(acc[r], lo, hi);
                    const float s0 = keep ? lo * SCALEF : NEGF;
                    const float s1 = keep ? hi * SCALEF : NEGF;
                    *(u64*)(SC + 2 * (lp * 52 + m)) = pk2(s0, s1);
                }
            }
        }
        __syncthreads();

        // ---- softmax per query row, * qmask ----
        if (tid < LL) {
            const int lp = tid % 25, h = tid / 25;
            float* base = SC + 2 * (lp * 52) + h;
            float mx = base[0];
#pragma unroll
            for (int m = 1; m < 50; ++m) mx = fmaxf(mx, base[2 * m]);
            float s = 0.0f;
#pragma unroll
            for (int m = 0; m < 50; ++m) {
                const float e = expf(base[2 * m] - mx);
                base[2 * m] = e;
                s += e;
            }
            const float inv = RM[tid] / s;
#pragma unroll
            for (int m = 0; m < 50; ++m) base[2 * m] *= inv;
        }
        __syncthreads();

        // ---- x += attn @ V  (lp range split across two halves) ----
        if (tid < 400) {
            const int d  = tid % 200;
            const int h  = tid / 200;          // 0 or 1
            const int lp0 = h ? 13 : 0;
            const int NL  = h ? 12 : 13;
            u64 acc[13];
#pragma unroll
            for (int i = 0; i < 13; ++i) acc[i] = 0;
#pragma unroll 2
            for (int m = 0; m < 50; ++m) {
                const float v = VB[m * 201 + d];
                const u64 pv = pk2(v, v);
#pragma unroll
                for (int i = 0; i < 13; ++i) {
                    if (i < NL) {
                        const u64 a = *(const u64*)(SC + 2 * ((lp0 + i) * 52 + m));
                        acc[i] = fma2(a, pv, acc[i]);
                    }
                }
            }
#pragma unroll
            for (int i = 0; i < 13; ++i) {
                if (i < NL) {
                    u64* p = (u64*)(XI + 2 * ((lp0 + i) * DD + d));
                    *p = add2(*p, acc[i]);
                }
            }
        }
        __syncthreads();

        // ---- FFN: h1 = relu(x@W1+b1) (pairs), h2 = h1@W2+b2 (row-major-201) ----
        mm200p<true, true >(XI, w1, b1v, QB, tid);
        __syncthreads();
        mm200p<false, false>(QB, w2, b2v, KB, tid);
        __syncthreads();

        // ---- layernorm(h2)*g + b + x -> x ----
        // sum partials: 400 threads, 25 elems each (l = tid>>3, q = tid&7)
        if (tid < 400) {
            const int l = tid >> 3, q = tid & 7;
            const float* row = KB + l * 201 + q * 25;
            float s = 0.0f;
#pragma unroll
            for (int k = 0; k < 25; ++k) s += row[k];
            REDF[tid] = s;
        }
        __syncthreads();
        if (tid < LL) {
            float s = 0.0f;
#pragma unroll
            for (int j = 0; j < 8; ++j) s += REDF[tid * 8 + j];
            MU[tid] = s * (1.0f / DD);
        }
        __syncthreads();
        if (tid < 400) {
            const int l = tid >> 3, q = tid & 7;
            const float mu = MU[l];
            const float* row = KB + l * 201 + q * 25;
            float s = 0.0f;
#pragma unroll
            for (int k = 0; k < 25; ++k) {
                const float dv = row[k] - mu;
                s = fmaf(dv, dv, s);
            }
            REDF[tid] = s;
        }
        __syncthreads();
        if (tid < LL) {
            float s = 0.0f;
#pragma unroll
            for (int j = 0; j < 8; ++j) s += REDF[tid * 8 + j];
            RSD[tid] = rsqrtf(s * (1.0f / DD) + EPSF);
        }
        __syncthreads();
        if (tid < 400) {
            const int d = tid % 200;
            const int h = tid / 200;
            const int lp0 = h ? 13 : 0;
            const int NL  = h ? 12 : 13;
            const float gd = gv[d];
            const float bd = bnv[d];
#pragma unroll 1
            for (int i = 0; i < NL; ++i) {
                const int lp = lp0 + i;
                const float lo = (KB[lp * 201 + d]        - MU[lp])      * RSD[lp]      * gd + bd;
                const float hi = (KB[(lp + 25) * 201 + d] - MU[lp + 25]) * RSD[lp + 25] * gd + bd;
                u64* p = (u64*)(XI + 2 * (lp * DD + d));
                *p = add2(*p, pk2(lo, hi));
            }
        }
        __syncthreads();
    }

    // ---- write result (de-interleave) ----
    float* ob = out + (size_t)b * LL * DD;
    for (int i = tid; i < LP * DD; i += NTH) {
        const int lp = i / DD;
        const int d  = i - lp * DD;
        float lo, hi;
        upk2(*(const u64*)(XI + 2 * i), lo, hi);
        ob[lp * DD + d] = lo;
        ob[(lp + 25) * DD + d] = hi;
    }
}

extern "C" void kernel_launch(void* const* d_in, const int* in_sizes, int n_in,
                              void* d_out, int out_size) {
    (void)in_sizes; (void)n_in; (void)out_size;
    const int*   tokens = (const int*)  d_in[0];
    const float* emb    = (const float*)d_in[1];
    const float* Wq     = (const float*)d_in[2];
    const float* bq     = (const float*)d_in[3];
    const float* Wk     = (const float*)d_in[4];
    const float* bk     = (const float*)d_in[5];
    const float* Wv     = (const float*)d_in[6];
    const float* bv     = (const float*)d_in[7];
    const float* W1     = (const float*)d_in[8];
    const float* b1     = (const float*)d_in[9];
    const float* W2     = (const float*)d_in[10];
    const float* b2     = (const float*)d_in[11];
    const float* lng    = (const float*)d_in[12];
    const float* lnb    = (const float*)d_in[13];
    float* out = (float*)d_out;

    cudaFuncSetAttribute(transformer_rows_kernel,
                         cudaFuncAttributeMaxDynamicSharedMemorySize, SMEM_BYTES);
    transformer_rows_kernel<<<BB, NTH, SMEM_BYTES>>>(
        tokens, emb, Wq, bq, Wk, bk, Wv, bv, W1, b1, W2, b2, lng, lnb, out);
}